// round 15
// baseline (speedup 1.0000x reference)
#include <cuda_runtime.h>
#include <cuda_fp16.h>

#define B_ 32
#define K_ 64
#define W_ 100
#define H_ 150
#define G_ 450
#define KW_ 6400
#define ALPHA_ 0.2f
#define THRES_ 0.0002f

// ---------------- scratch ----------------
__device__ float g_Wx[B_*K_*W_];
__device__ float g_cx[B_*K_*W_];
__device__ float g_glwihT[W_*G_];
__device__ float2 g_glwhhP[(H_/2)*G_];
__device__ float g_muT[H_*H_];
__device__ float g_stdT[H_*H_];
__device__ float g_gxg[K_*B_*G_];
__device__ float g_hl[B_*H_];
__device__ float g_z[B_*H_];
__device__ __half g_gxnet_h[K_*B_*K_*G_];        // [k][s][b][g]

// ---------------- helpers ----------------
__device__ __forceinline__ unsigned long long pk2(float a, float b){
    unsigned long long r;
    asm("mov.b64 %0, {%1,%2};" : "=l"(r) : "f"(a), "f"(b));
    return r;
}
__device__ __forceinline__ void fma2(unsigned long long &d, unsigned long long a, unsigned long long b){
    asm("fma.rn.f32x2 %0, %1, %2, %0;" : "+l"(d) : "l"(a), "l"(b));
}
__device__ __forceinline__ float2 up2(unsigned long long v){
    float a, b;
    asm("mov.b64 {%0,%1}, %2;" : "=f"(a), "=f"(b) : "l"(v));
    float2 r; r.x = a; r.y = b; return r;
}
__device__ __forceinline__ float sigf(float x){ return __fdividef(1.f, 1.f + __expf(-x)); }
__device__ __forceinline__ float tanhf_(float x){
    float e = __expf(2.f * x);
    return 1.f - __fdividef(2.f, e + 1.f);
}
__device__ __forceinline__ float tanha(float x){
    float r; asm("tanh.approx.f32 %0, %1;" : "=f"(r) : "f"(x)); return r;
}
__device__ __forceinline__ float siga(float x){ return fmaf(0.5f, tanha(0.5f*x), 0.5f); }
__device__ __forceinline__ unsigned cta_rank(){
    unsigned r; asm("mov.u32 %0, %%cluster_ctarank;" : "=r"(r)); return r;
}
__device__ __forceinline__ void cluster_sync(){
    asm volatile("barrier.cluster.arrive.aligned;" ::: "memory");
    asm volatile("barrier.cluster.wait.aligned;"  ::: "memory");
}
__device__ __forceinline__ void st_peer_f32(float* local_ptr, unsigned peer, float v){
    unsigned la = (unsigned)__cvta_generic_to_shared(local_ptr);
    unsigned ra;
    asm volatile("mapa.shared::cluster.u32 %0, %1, %2;" : "=r"(ra) : "r"(la), "r"(peer));
    asm volatile("st.shared::cluster.f32 [%0], %1;" :: "r"(ra), "f"(v) : "memory");
}
__device__ __forceinline__ void mma16816(float* c, const unsigned* a, unsigned b0, unsigned b1){
    asm volatile("mma.sync.aligned.m16n8k16.row.col.f32.f16.f16.f32 "
        "{%0,%1,%2,%3}, {%4,%5,%6,%7}, {%8,%9}, {%0,%1,%2,%3};"
        : "+f"(c[0]), "+f"(c[1]), "+f"(c[2]), "+f"(c[3])
        : "r"(a[0]), "r"(a[1]), "r"(a[2]), "r"(a[3]), "r"(b0), "r"(b1));
}

// ---------------- prep (side stream) ----------------
__global__ void k_prep(const float* gl_wih, const float* gl_whh,
                       const float* mu_w, const float* std_w)
{
    int tid = blockIdx.x * blockDim.x + threadIdx.x;
    int stride = gridDim.x * blockDim.x;
    for (int e = tid; e < G_*W_; e += stride){
        int g = e / W_, i = e % W_;
        g_glwihT[i*G_ + g] = gl_wih[e];
    }
    for (int e = tid; e < (H_/2)*G_; e += stride){
        int i2 = e / G_, g = e % G_;
        float2 v;
        v.x = gl_whh[g*H_ + 2*i2];
        v.y = gl_whh[g*H_ + 2*i2 + 1];
        g_glwhhP[e] = v;
    }
    for (int e = tid; e < H_*H_; e += stride){
        int o = e / H_, i = e % H_;
        g_muT[i*H_ + o]  = mu_w[e];
        g_stdT[i*H_ + o] = std_w[e];
    }
}

// ---------------- K1: Wx ----------------
__global__ void k_wx(const float* __restrict__ x, const float* __restrict__ lin_w,
                     const float* __restrict__ lin_b)
{
    __shared__ float xs[W_];
    int row = blockIdx.x;
    int t = threadIdx.x;
    if (t < W_) xs[t] = x[row*W_ + t];
    __syncthreads();
    if (t < W_){
        float acc = lin_b[t];
        const float* lw = lin_w + t*W_;
        #pragma unroll 4
        for (int i = 0; i < W_; i++) acc += xs[i] * lw[i];
        g_Wx[row*W_ + t] = acc;
    }
}

// ---------------- K2: attention ----------------
__global__ __launch_bounds__(256) void k_attn(const float* __restrict__ y,
                       const float* __restrict__ a, const float* __restrict__ bias)
{
    int b = blockIdx.x >> 6;
    int k = blockIdx.x & 63;
    const float a0 = a[0], a1 = a[1];
    const float yb = a0 * y[b*K_ + k];
    const float* vrow = g_Wx + b*KW_;
    const float* brow = bias + k*KW_;
    int t = threadIdx.x;             // 256

    __shared__ float red[256];

    float e_loc[25], v_loc[25];
    float m = -3.4e38f;
    #pragma unroll
    for (int jj = 0; jj < 25; jj++){
        int j = t + jj*256;
        float v = vrow[j];
        float e = yb + a1*v + brow[j];
        e = e > 0.f ? e : ALPHA_*e;
        e_loc[jj] = e; v_loc[jj] = v;
        m = fmaxf(m, e);
    }
    red[t] = m; __syncthreads();
    for (int o = 128; o > 0; o >>= 1){
        if (t < o) red[t] = fmaxf(red[t], red[t+o]);
        __syncthreads();
    }
    float M = red[0]; __syncthreads();

    float ssum = 0.f;
    #pragma unroll
    for (int jj = 0; jj < 25; jj++) ssum += __expf(e_loc[jj] - M);
    red[t] = ssum; __syncthreads();
    for (int o = 128; o > 0; o >>= 1){
        if (t < o) red[t] += red[t+o];
        __syncthreads();
    }
    float S = red[0]; __syncthreads();

    float T = M + __logf(THRES_ * S);

    float acc = 0.f;
    #pragma unroll
    for (int jj = 0; jj < 25; jj++) if (e_loc[jj] >= T) acc += v_loc[jj];
    red[t] = acc; __syncthreads();
    for (int o = 128; o > 0; o >>= 1){
        if (t < o) red[t] += red[t+o];
        __syncthreads();
    }
    float sbk = red[0];

    if (t < W_){
        int row = b*K_ + k;
        g_cx[row*W_ + t] = g_Wx[row*W_ + t] + sbk;
    }
}

// ---------------- K3: gx for global GRU ----------------
__global__ void k_gxg(const float* __restrict__ gl_bih)
{
    int s = blockIdx.x >> 5;
    int b = blockIdx.x & 31;
    __shared__ float cx[W_];
    int t = threadIdx.x;             // 512
    if (t < W_) cx[t] = g_cx[(b*K_ + s)*W_ + t];
    __syncthreads();
    if (t < G_){
        float acc = gl_bih[t];
        #pragma unroll 4
        for (int i = 0; i < W_; i++) acc += cx[i] * g_glwihT[i*G_ + t];
        g_gxg[(s*B_ + b)*G_ + t] = acc;
    }
}

// ---------------- K4: global GRU (cluster 2, smem weights) ----------------
#define GL_W    0
#define GL_H0   33752
#define GL_H1   33912
#define GL_GH   34072
#define GL_BHH  34304
#define GL_SMEM_FLOATS (GL_BHH + 232)

__global__ __launch_bounds__(256, 1) __cluster_dims__(2,1,1)
void k_gru_gl(const float* __restrict__ gl_bhh)
{
    extern __shared__ __align__(16) float smg[];
    int b = blockIdx.x >> 1;
    unsigned hf = cta_rank();
    unsigned peer = hf ^ 1u;
    int t = threadIdx.x;             // 256

    float2* w2_sh  = (float2*)(smg + GL_W);
    float*  gh_sh  = smg + GL_GH;
    float*  bhh_sh = smg + GL_BHH;

    for (int e = t; e < 75*225; e += 256){
        int i2 = e / 225, c = e - i2*225;
        int gcol = (c/75)*H_ + (int)hf*75 + (c%75);
        w2_sh[e] = g_glwhhP[i2*G_ + gcol];
    }
    if (t < 225){
        int gcol = (t/75)*H_ + (int)hf*75 + (t%75);
        bhh_sh[t] = gl_bhh[gcol];
    }
    if (t < 152){ smg[GL_H0 + t] = 0.f; smg[GL_H1 + t] = 0.f; }
    cluster_sync();

    int cur = 0;
    for (int s = 0; s < 64; s++){
        float* h_cur = smg + (cur ? GL_H1 : GL_H0);
        float* h_nxt = smg + (cur ? GL_H0 : GL_H1);

        if (t < 225){
            unsigned long long acc = 0ull;
            const unsigned long long* hp = (const unsigned long long*)h_cur;
            const float2* wc = w2_sh + t;
            #pragma unroll 5
            for (int i2 = 0; i2 < 75; i2++){
                unsigned long long w2 = *(const unsigned long long*)(wc + i2*225);
                fma2(acc, w2, hp[i2]);
            }
            float2 v = up2(acc);
            gh_sh[t] = v.x + v.y + bhh_sh[t];
        }
        __syncthreads();

        if (t < 75){
            int j = (int)hf*75 + t;
            const float* gx = g_gxg + (s*B_ + b)*G_;
            float r  = sigf(gx[j]        + gh_sh[t]);
            float zz = sigf(gx[H_ + j]   + gh_sh[75 + t]);
            float n  = tanhf_(gx[2*H_+j] + r * gh_sh[150 + t]);
            float hnew = (1.f - zz)*n + zz*h_cur[j];
            h_nxt[j] = hnew;
            st_peer_f32(&h_nxt[j], peer, hnew);
        }
        cluster_sync();
        cur ^= 1;
    }
    float* hfin = smg + (cur ? GL_H1 : GL_H0);
    if (t < 75){
        int j = (int)hf*75 + t;
        g_hl[b*H_ + j] = hfin[j];
    }
}

// ---------------- K5: z ----------------
__global__ void k_z(const float* __restrict__ mu_b, const float* __restrict__ std_b,
                    const float* __restrict__ z_noise)
{
    int b = blockIdx.x, t = threadIdx.x;   // 160
    __shared__ float hs[152];
    if (t < H_) hs[t] = g_hl[b*H_ + t];
    __syncthreads();
    if (t < H_){
        float mu = mu_b[t], lv = std_b[t];
        #pragma unroll 2
        for (int i = 0; i < H_; i++){
            float h = hs[i];
            mu += h * g_muT[i*H_ + t];
            lv += h * g_stdT[i*H_ + t];
        }
        g_z[b*H_ + t] = mu + __expf(0.5f*lv) * z_noise[b*H_ + t];
    }
}

// ---------------- K6: gxnet GEMM — reg-pipelined staging + zero-tile skip ------
#define GXM_GH0  0
#define GXM_GH1  9216
#define GXM_BUF  18432
#define GXM_BI   21312
#define GXM_SMEM_FLOATS 21768

__global__ __launch_bounds__(512, 1)
void k_gxnet(const float* __restrict__ net_wih, const float* __restrict__ net_bih)
{
    extern __shared__ __align__(16) float sm6[];
    float*  gh0   = sm6 + GXM_GH0;
    float*  gh1   = sm6 + GXM_GH1;
    __half* bufs  = (__half*)(sm6 + GXM_BUF);  // 3 x [16][120]
    float*  bi_sh = sm6 + GXM_BI;

    int k = blockIdx.x >> 2;
    int q = blockIdx.x & 3;
    int t = threadIdx.x;             // 512
    int w = t >> 5, l = t & 31;
    int g = l >> 2, tg = l & 3;
    const bool has_t1 = ((w + 16)*16) < G_;    // warps 13-15: tile1 all-zero, skip

    unsigned Af[2][7][4];
    const float* wsrc = net_wih + k*(G_*W_);
    #pragma unroll
    for (int tile = 0; tile < 2; tile++){
        int mt = tile ? (w + 16) : w;
        #pragma unroll
        for (int kc = 0; kc < 7; kc++){
            #pragma unroll
            for (int qq = 0; qq < 4; qq++){
                int m = mt*16 + g + ((qq & 1) ? 8 : 0);
                int i = kc*16 + 2*tg + ((qq >= 2) ? 8 : 0);
                unsigned val = 0u;
                if (m < G_ && i < W_){
                    float2 f = *(const float2*)&wsrc[m*W_ + i];
                    __half2 h2 = __floats2half2_rn(f.x, f.y);
                    val = *(unsigned*)&h2;
                }
                Af[tile][kc][qq] = val;
            }
        }
    }

    if (t < 452) bi_sh[t] = (t < G_) ? net_bih[k*G_ + t] : 0.f;
    for (int e = t; e < 480; e += 512){
        int bsel = e / 160, ee = e % 160;
        int rp = ee / 10, c2 = ee % 10;
        *(__half2*)&bufs[bsel*1920 + rp*120 + 100 + 2*c2] = __floats2half2_rn(0.f, 0.f);
    }

    int r0 = q*512;

    // prologue: block0 -> regs -> buf0; block1 -> regs
    float2 pfA0, pfA1, pfB0, pfB1;
    pfA1.x = 0.f; pfA1.y = 0.f; pfB1.x = 0.f; pfB1.y = 0.f;
    {
        const float* Ab = g_Wx + r0*W_;
        { int rp = t / 50, ip = t % 50;
          if (t < 800) pfA0 = *(const float2*)&Ab[rp*W_ + 2*ip]; else {pfA0.x=0.f;pfA0.y=0.f;} }
        { int e = t + 512; int rp = e / 50, ip = e % 50;
          if (e < 800) pfA1 = *(const float2*)&Ab[rp*W_ + 2*ip]; }
        { int rp = t / 50, ip = t % 50;
          if (t < 800) *(__half2*)&bufs[rp*120 + 2*ip] = __floats2half2_rn(pfA0.x, pfA0.y); }
        { int e = t + 512; int rp = e / 50, ip = e % 50;
          if (e < 800) *(__half2*)&bufs[rp*120 + 2*ip] = __floats2half2_rn(pfA1.x, pfA1.y); }
        const float* Ab1p = g_Wx + (r0 + 16)*W_;
        { int rp = t / 50, ip = t % 50;
          if (t < 800) pfA0 = *(const float2*)&Ab1p[rp*W_ + 2*ip]; }
        { int e = t + 512; int rp = e / 50, ip = e % 50;
          if (e < 800) pfA1 = *(const float2*)&Ab1p[rp*W_ + 2*ip]; }
    }

    float c[2][2][4];

    for (int it = 0; it < 32; it++){
        __half* bcur = bufs + (it % 3)*1920;
        float*  gcur = (it & 1) ? gh1 : gh0;

        if (it < 30){
            const float* Ab = g_Wx + (r0 + (it + 2)*16)*W_;
            { int rp = t / 50, ip = t % 50;
              if (t < 800) pfB0 = *(const float2*)&Ab[rp*W_ + 2*ip]; }
            { int e = t + 512; int rp = e / 50, ip = e % 50;
              if (e < 800) pfB1 = *(const float2*)&Ab[rp*W_ + 2*ip]; }
        }
        if (it < 31){
            __half* bnxt = bufs + ((it + 1) % 3)*1920;
            { int rp = t / 50, ip = t % 50;
              if (t < 800) *(__half2*)&bnxt[rp*120 + 2*ip] = __floats2half2_rn(pfA0.x, pfA0.y); }
            { int e = t + 512; int rp = e / 50, ip = e % 50;
              if (e < 800) *(__half2*)&bnxt[rp*120 + 2*ip] = __floats2half2_rn(pfA1.x, pfA1.y); }
        }
        __syncthreads();

        if (it > 0){
            float* gprev = (it & 1) ? gh0 : gh1;
            int rprev = r0 + (it - 1)*16;
            for (int e = t; e < 3600; e += 512){
                int rr = e / 225, mp = e % 225;
                int m0 = 2*mp;
                float v0 = gprev[m0*18 + rr]       + bi_sh[m0];
                float v1 = gprev[(m0 + 1)*18 + rr] + bi_sh[m0 + 1];
                int r = rprev + rr;
                long long o = (long long)(k*2048 + (r & 63)*B_ + (r >> 6))*G_ + m0;
                *(__half2*)&g_gxnet_h[o] = __floats2half2_rn(v0, v1);
            }
        }

        #pragma unroll
        for (int x1 = 0; x1 < 2; x1++)
            #pragma unroll
            for (int x2 = 0; x2 < 2; x2++)
                #pragma unroll
                for (int x3 = 0; x3 < 4; x3++) c[x1][x2][x3] = 0.f;

        const __half* hr0 = bcur + g*120 + 2*tg;
        const __half* hr1 = hr0 + 8*120;
        if (has_t1){
            #pragma unroll
            for (int kc = 0; kc < 7; kc++){
                unsigned b00 = *(const unsigned*)&hr0[kc*16];
                unsigned b01 = *(const unsigned*)&hr0[kc*16 + 8];
                unsigned b10 = *(const unsigned*)&hr1[kc*16];
                unsigned b11 = *(const unsigned*)&hr1[kc*16 + 8];
                mma16816(c[0][0], Af[0][kc], b00, b01);
                mma16816(c[0][1], Af[0][kc], b10, b11);
                mma16816(c[1][0], Af[1][kc], b00, b01);
                mma16816(c[1][1], Af[1][kc], b10, b11);
            }
        } else {
            #pragma unroll
            for (int kc = 0; kc < 7; kc++){
                unsigned b00 = *(const unsigned*)&hr0[kc*16];
                unsigned b01 = *(const unsigned*)&hr0[kc*16 + 8];
                unsigned b10 = *(const unsigned*)&hr1[kc*16];
                unsigned b11 = *(const unsigned*)&hr1[kc*16 + 8];
                mma16816(c[0][0], Af[0][kc], b00, b01);
                mma16816(c[0][1], Af[0][kc], b10, b11);
            }
        }

        {
            int m0a = w*16 + g;
            #pragma unroll
            for (int nt = 0; nt < 2; nt++){
                int col = nt*8 + 2*tg;
                *(float2*)&gcur[(m0a    )*18 + col] = make_float2(c[0][nt][0], c[0][nt][1]);
                *(float2*)&gcur[(m0a + 8)*18 + col] = make_float2(c[0][nt][2], c[0][nt][3]);
            }
            if (has_t1){
                int m0b = (w + 16)*16 + g;
                #pragma unroll
                for (int nt = 0; nt < 2; nt++){
                    int col = nt*8 + 2*tg;
                    *(float2*)&gcur[(m0b    )*18 + col] = make_float2(c[1][nt][0], c[1][nt][1]);
                    *(float2*)&gcur[(m0b + 8)*18 + col] = make_float2(c[1][nt][2], c[1][nt][3]);
                }
            }
        }

        pfA0 = pfB0; pfA1 = pfB1;
    }

    __syncthreads();
    {
        int rprev = r0 + 31*16;
        for (int e = t; e < 3600; e += 512){
            int rr = e / 225, mp = e % 225;
            int m0 = 2*mp;
            float v0 = gh1[m0*18 + rr]       + bi_sh[m0];
            float v1 = gh1[(m0 + 1)*18 + rr] + bi_sh[m0 + 1];
            int r = rprev + rr;
            long long o = (long long)(k*2048 + (r & 63)*B_ + (r >> 6))*G_ + m0;
            *(__half2*)&g_gxnet_h[o] = __floats2half2_rn(v0, v1);
        }
    }
}

// ---------------- K7: net GRUs — mma.sync + gx prefetch + zero-tile skip -------
#define GRN_GHO  0                    // gh fp32 [512][18]
#define GRN_HO   9216                 // h  fp32 [150][18]
#define GRN_HTO  11916                // hT fp16 [16][168]
#define GRN_BHO  13260                // bhh fp32 [452]
#define GRN_SMEM_FLOATS (13260 + 452)

__global__ __launch_bounds__(512, 1)
void k_gru_net(const float* __restrict__ net_whh, const float* __restrict__ net_bhh,
               float* __restrict__ out)
{
    extern __shared__ __align__(16) float sm7[];
    float*  gh_sh  = sm7 + GRN_GHO;
    float*  h_sh   = sm7 + GRN_HO;
    __half* hT     = (__half*)(sm7 + GRN_HTO);
    float*  bhh_sh = sm7 + GRN_BHO;

    int k  = blockIdx.x >> 1;
    int b0 = (blockIdx.x & 1) * 16;
    int t  = threadIdx.x;             // 512
    int w  = t >> 5, l = t & 31;
    int g  = l >> 2, tg = l & 3;
    const bool has_t1 = ((w + 16)*16) < G_;

    unsigned Af[2][10][4];
    const float* wsrc = net_whh + k*(G_*H_);
    #pragma unroll
    for (int tile = 0; tile < 2; tile++){
        int mt = tile ? (w + 16) : w;
        #pragma unroll
        for (int kc = 0; kc < 10; kc++){
            #pragma unroll
            for (int qq = 0; qq < 4; qq++){
                int m = mt*16 + g + ((qq & 1) ? 8 : 0);
                int i = kc*16 + 2*tg + ((qq >= 2) ? 8 : 0);
                unsigned val = 0u;
                if (m < G_ && i < H_){
                    float2 f = *(const float2*)&wsrc[m*H_ + i];
                    __half2 h2 = __floats2half2_rn(f.x, f.y);
                    val = *(unsigned*)&h2;
                }
                Af[tile][kc][qq] = val;
            }
        }
    }

    for (int e = t; e < H_*16; e += 512){
        int j = e % H_, bb = e / H_;
        float hv = g_z[(b0 + bb)*H_ + j];
        h_sh[j*18 + bb] = hv;
        hT[bb*168 + j] = __float2half(hv);
    }
    for (int e = t; e < 16*18; e += 512){
        int bb = e / 18, c = e % 18;
        hT[bb*168 + 150 + c] = __half(0.f);
    }
    if (t < 452) bhh_sh[t] = (t < G_) ? net_bhh[k*G_ + t] : 0.f;
    __syncthreads();

    const __half* gxk = g_gxnet_h + (long long)k*2048*G_;

    for (int s = 0; s < 64; s++){
        float pgx[3][6];
        #pragma unroll
        for (int u = 0; u < 3; u++){
            int e = t + u*512;
            if (e < 1200){
                int j = e % H_, bp = e / H_;
                const __half* gx0 = gxk + (long long)(s*B_ + b0 + 2*bp)*G_ + j;
                pgx[u][0] = __half2float(gx0[0]);
                pgx[u][1] = __half2float(gx0[H_]);
                pgx[u][2] = __half2float(gx0[2*H_]);
                pgx[u][3] = __half2float(gx0[G_]);
                pgx[u][4] = __half2float(gx0[G_ + H_]);
                pgx[u][5] = __half2float(gx0[G_ + 2*H_]);
            }
        }

        float c[2][2][4];
        #pragma unroll
        for (int x1 = 0; x1 < 2; x1++)
            #pragma unroll
            for (int x2 = 0; x2 < 2; x2++)
                #pragma unroll
                for (int x3 = 0; x3 < 4; x3++) c[x1][x2][x3] = 0.f;

        const __half* hr0 = hT + g*168 + 2*tg;
        const __half* hr1 = hr0 + 8*168;
        if (has_t1){
            #pragma unroll
            for (int kc = 0; kc < 10; kc++){
                unsigned b00 = *(const unsigned*)&hr0[kc*16];
                unsigned b01 = *(const unsigned*)&hr0[kc*16 + 8];
                unsigned b10 = *(const unsigned*)&hr1[kc*16];
                unsigned b11 = *(const unsigned*)&hr1[kc*16 + 8];
                mma16816(c[0][0], Af[0][kc], b00, b01);
                mma16816(c[0][1], Af[0][kc], b10, b11);
                mma16816(c[1][0], Af[1][kc], b00, b01);
                mma16816(c[1][1], Af[1][kc], b10, b11);
            }
        } else {
            #pragma unroll
            for (int kc = 0; kc < 10; kc++){
                unsigned b00 = *(const unsigned*)&hr0[kc*16];
                unsigned b01 = *(const unsigned*)&hr0[kc*16 + 8];
                unsigned b10 = *(const unsigned*)&hr1[kc*16];
                unsigned b11 = *(const unsigned*)&hr1[kc*16 + 8];
                mma16816(c[0][0], Af[0][kc], b00, b01);
                mma16816(c[0][1], Af[0][kc], b10, b11);
            }
        }

        {
            int m0a = w*16 + g;
            #pragma unroll
            for (int nt = 0; nt < 2; nt++){
                int col = nt*8 + 2*tg;
                *(float2*)&gh_sh[(m0a    )*18 + col] = make_float2(c[0][nt][0], c[0][nt][1]);
                *(float2*)&gh_sh[(m0a + 8)*18 + col] = make_float2(c[0][nt][2], c[0][nt][3]);
            }
            if (has_t1){
                int m0b = (w + 16)*16 + g;
                #pragma unroll
                for (int nt = 0; nt < 2; nt++){
                    int col = nt*8 + 2*tg;
                    *(float2*)&gh_sh[(m0b    )*18 + col] = make_float2(c[1][nt][0], c[1][nt][1]);
                    *(float2*)&gh_sh[(m0b + 8)*18 + col] = make_float2(c[1][nt][2], c[1][nt][3]);
                }
            }
        }
        __syncthreads();

        #pragma unroll
        for (int u = 0; u < 3; u++){
            int e = t + u*512;
            if (e < 1200){
                int j = e % H_, bp = e / H_;
                int bb0 = 2*bp, bb1 = bb0 + 1;
                float bhr = bhh_sh[j];
                float bhz = bhh_sh[H_ + j];
                float bhn = bhh_sh[2*H_ + j];
                float ghr0 = gh_sh[(j       )*18 + bb0] + bhr;
                float ghz0 = gh_sh[(H_  + j )*18 + bb0] + bhz;
                float ghn0 = gh_sh[(2*H_+ j )*18 + bb0] + bhn;
                float ghr1 = gh_sh[(j       )*18 + bb1] + bhr;
                float ghz1 = gh_sh[(H_  + j )*18 + bb1] + bhz;
                float ghn1 = gh_sh[(2*H_+ j )*18 + bb1] + bhn;
                float r0  = siga(pgx[u][0] + ghr0);
                float zz0 = siga(pgx[u][1] + ghz0);
                float n0  = tanha(pgx[u][2] + r0*ghn0);
                float r1  = siga(pgx[u][3] + ghr1);
                float zz1 = siga(pgx[u][4] + ghz1);
                float n1  = tanha(pgx[u][5] + r1*ghn1);
                float h0o = h_sh[j*18 + bb0];
                float h1o = h_sh[j*18 + bb1];
                float hn0 = (1.f - zz0)*n0 + zz0*h0o;
                float hn1 = (1.f - zz1)*n1 + zz1*h1o;
                h_sh[j*18 + bb0] = hn0;
                h_sh[j*18 + bb1] = hn1;
                hT[bb0*168 + j] = __float2half(hn0);
                hT[bb1*168 + j] = __float2half(hn1);
            }
        }
        __syncthreads();
    }

    for (int e = t; e < H_*16; e += 512){
        int j = e % H_, bb = e / H_;
        out[(b0 + bb)*(K_*H_) + k*H_ + j] = h_sh[j*18 + bb];
    }
}

// ---------------- launch (R10/R14 schedule) ----------------
extern "C" void kernel_launch(void* const* d_in, const int* in_sizes, int n_in,
                              void* d_out, int out_size)
{
    const float* x       = (const float*)d_in[0];
    const float* y       = (const float*)d_in[1];
    const float* z_noise = (const float*)d_in[2];
    const float* lin_w   = (const float*)d_in[3];
    const float* lin_b   = (const float*)d_in[4];
    const float* a       = (const float*)d_in[5];
    const float* bias    = (const float*)d_in[6];
    const float* gl_wih  = (const float*)d_in[7];
    const float* gl_whh  = (const float*)d_in[8];
    const float* gl_bih  = (const float*)d_in[9];
    const float* gl_bhh  = (const float*)d_in[10];
    const float* mu_w    = (const float*)d_in[11];
    const float* mu_b    = (const float*)d_in[12];
    const float* std_w   = (const float*)d_in[13];
    const float* std_b   = (const float*)d_in[14];
    const float* net_wih = (const float*)d_in[15];
    const float* net_whh = (const float*)d_in[16];
    const float* net_bih = (const float*)d_in[17];
    const float* net_bhh = (const float*)d_in[18];
    float* out = (float*)d_out;

    static cudaStream_t s_side = nullptr;
    static cudaEvent_t ev1 = nullptr, ev2 = nullptr;
    if (!s_side){
        cudaStreamCreateWithFlags(&s_side, cudaStreamNonBlocking);
        cudaEventCreateWithFlags(&ev1, cudaEventDisableTiming);
        cudaEventCreateWithFlags(&ev2, cudaEventDisableTiming);
        cudaFuncSetAttribute(k_gxnet,   cudaFuncAttributeMaxDynamicSharedMemorySize,
                             GXM_SMEM_FLOATS*4);
        cudaFuncSetAttribute(k_gru_net, cudaFuncAttributeMaxDynamicSharedMemorySize,
                             GRN_SMEM_FLOATS*4);
        cudaFuncSetAttribute(k_gru_gl,  cudaFuncAttributeMaxDynamicSharedMemorySize,
                             GL_SMEM_FLOATS*4);
    }

    k_prep<<<256, 256, 0, s_side>>>(gl_wih, gl_whh, mu_w, std_w);

    k_wx<<<B_*K_, 128>>>(x, lin_w, lin_b);
    cudaEventRecord(ev1, 0);

    k_gxnet<<<K_*4, 512, GXM_SMEM_FLOATS*4>>>(net_wih, net_bih);

    cudaStreamWaitEvent(s_side, ev1, 0);
    k_attn<<<B_*K_, 256, 0, s_side>>>(y, a, bias);
    k_gxg<<<K_*B_, 512, 0, s_side>>>(gl_bih);
    k_gru_gl<<<B_*2, 256, GL_SMEM_FLOATS*4, s_side>>>(gl_bhh);
    k_z<<<B_, 160, 0, s_side>>>(mu_b, std_b, z_noise);
    cudaEventRecord(ev2, s_side);

    cudaStreamWaitEvent(0, ev2, 0);
    k_gru_net<<<K_*2, 512, GRN_SMEM_FLOATS*4>>>(net_whh, net_bhh, out);
}

// round 16
// speedup vs baseline: 1.0333x; 1.0333x over previous
#include <cuda_runtime.h>
#include <cuda_fp16.h>

#define B_ 32
#define K_ 64
#define W_ 100
#define H_ 150
#define G_ 450
#define KW_ 6400
#define ALPHA_ 0.2f
#define THRES_ 0.0002f

// ---------------- scratch ----------------
__device__ float g_Wx[B_*K_*W_];
__device__ float g_cx[B_*K_*W_];
__device__ float g_glwihT[W_*G_];
__device__ float2 g_glwhhP[(H_/2)*G_];
__device__ float g_muT[H_*H_];
__device__ float g_stdT[H_*H_];
__device__ float g_gxg[K_*B_*G_];
__device__ float g_hl[B_*H_];
__device__ float g_z[B_*H_];
__device__ __half g_gxnet_h[K_*B_*K_*G_];        // [k][s][b][g]

// ---------------- helpers ----------------
__device__ __forceinline__ unsigned long long pk2(float a, float b){
    unsigned long long r;
    asm("mov.b64 %0, {%1,%2};" : "=l"(r) : "f"(a), "f"(b));
    return r;
}
__device__ __forceinline__ void fma2(unsigned long long &d, unsigned long long a, unsigned long long b){
    asm("fma.rn.f32x2 %0, %1, %2, %0;" : "+l"(d) : "l"(a), "l"(b));
}
__device__ __forceinline__ float2 up2(unsigned long long v){
    float a, b;
    asm("mov.b64 {%0,%1}, %2;" : "=f"(a), "=f"(b) : "l"(v));
    float2 r; r.x = a; r.y = b; return r;
}
__device__ __forceinline__ float sigf(float x){ return __fdividef(1.f, 1.f + __expf(-x)); }
__device__ __forceinline__ float tanhf_(float x){
    float e = __expf(2.f * x);
    return 1.f - __fdividef(2.f, e + 1.f);
}
__device__ __forceinline__ float tanha(float x){
    float r; asm("tanh.approx.f32 %0, %1;" : "=f"(r) : "f"(x)); return r;
}
__device__ __forceinline__ float siga(float x){ return fmaf(0.5f, tanha(0.5f*x), 0.5f); }
__device__ __forceinline__ unsigned cta_rank(){
    unsigned r; asm("mov.u32 %0, %%cluster_ctarank;" : "=r"(r)); return r;
}
__device__ __forceinline__ void cluster_sync(){
    asm volatile("barrier.cluster.arrive.aligned;" ::: "memory");
    asm volatile("barrier.cluster.wait.aligned;"  ::: "memory");
}
__device__ __forceinline__ void st_peer_f32(float* local_ptr, unsigned peer, float v){
    unsigned la = (unsigned)__cvta_generic_to_shared(local_ptr);
    unsigned ra;
    asm volatile("mapa.shared::cluster.u32 %0, %1, %2;" : "=r"(ra) : "r"(la), "r"(peer));
    asm volatile("st.shared::cluster.f32 [%0], %1;" :: "r"(ra), "f"(v) : "memory");
}
__device__ __forceinline__ void mma16816(float* c, const unsigned* a, unsigned b0, unsigned b1){
    asm volatile("mma.sync.aligned.m16n8k16.row.col.f32.f16.f16.f32 "
        "{%0,%1,%2,%3}, {%4,%5,%6,%7}, {%8,%9}, {%0,%1,%2,%3};"
        : "+f"(c[0]), "+f"(c[1]), "+f"(c[2]), "+f"(c[3])
        : "r"(a[0]), "r"(a[1]), "r"(a[2]), "r"(a[3]), "r"(b0), "r"(b1));
}

// ---------------- prep (side stream) ----------------
__global__ void k_prep(const float* gl_wih, const float* gl_whh,
                       const float* mu_w, const float* std_w)
{
    int tid = blockIdx.x * blockDim.x + threadIdx.x;
    int stride = gridDim.x * blockDim.x;
    for (int e = tid; e < G_*W_; e += stride){
        int g = e / W_, i = e % W_;
        g_glwihT[i*G_ + g] = gl_wih[e];
    }
    for (int e = tid; e < (H_/2)*G_; e += stride){
        int i2 = e / G_, g = e % G_;
        float2 v;
        v.x = gl_whh[g*H_ + 2*i2];
        v.y = gl_whh[g*H_ + 2*i2 + 1];
        g_glwhhP[e] = v;
    }
    for (int e = tid; e < H_*H_; e += stride){
        int o = e / H_, i = e % H_;
        g_muT[i*H_ + o]  = mu_w[e];
        g_stdT[i*H_ + o] = std_w[e];
    }
}

// ---------------- K1: Wx ----------------
__global__ void k_wx(const float* __restrict__ x, const float* __restrict__ lin_w,
                     const float* __restrict__ lin_b)
{
    __shared__ float xs[W_];
    int row = blockIdx.x;
    int t = threadIdx.x;
    if (t < W_) xs[t] = x[row*W_ + t];
    __syncthreads();
    if (t < W_){
        float acc = lin_b[t];
        const float* lw = lin_w + t*W_;
        #pragma unroll 4
        for (int i = 0; i < W_; i++) acc += xs[i] * lw[i];
        g_Wx[row*W_ + t] = acc;
    }
}

// ---------------- K2: attention ----------------
__global__ __launch_bounds__(256) void k_attn(const float* __restrict__ y,
                       const float* __restrict__ a, const float* __restrict__ bias)
{
    int b = blockIdx.x >> 6;
    int k = blockIdx.x & 63;
    const float a0 = a[0], a1 = a[1];
    const float yb = a0 * y[b*K_ + k];
    const float* vrow = g_Wx + b*KW_;
    const float* brow = bias + k*KW_;
    int t = threadIdx.x;             // 256

    __shared__ float red[256];

    float e_loc[25], v_loc[25];
    float m = -3.4e38f;
    #pragma unroll
    for (int jj = 0; jj < 25; jj++){
        int j = t + jj*256;
        float v = vrow[j];
        float e = yb + a1*v + brow[j];
        e = e > 0.f ? e : ALPHA_*e;
        e_loc[jj] = e; v_loc[jj] = v;
        m = fmaxf(m, e);
    }
    red[t] = m; __syncthreads();
    for (int o = 128; o > 0; o >>= 1){
        if (t < o) red[t] = fmaxf(red[t], red[t+o]);
        __syncthreads();
    }
    float M = red[0]; __syncthreads();

    float ssum = 0.f;
    #pragma unroll
    for (int jj = 0; jj < 25; jj++) ssum += __expf(e_loc[jj] - M);
    red[t] = ssum; __syncthreads();
    for (int o = 128; o > 0; o >>= 1){
        if (t < o) red[t] += red[t+o];
        __syncthreads();
    }
    float S = red[0]; __syncthreads();

    float T = M + __logf(THRES_ * S);

    float acc = 0.f;
    #pragma unroll
    for (int jj = 0; jj < 25; jj++) if (e_loc[jj] >= T) acc += v_loc[jj];
    red[t] = acc; __syncthreads();
    for (int o = 128; o > 0; o >>= 1){
        if (t < o) red[t] += red[t+o];
        __syncthreads();
    }
    float sbk = red[0];

    if (t < W_){
        int row = b*K_ + k;
        g_cx[row*W_ + t] = g_Wx[row*W_ + t] + sbk;
    }
}

// ---------------- K3: gx for global GRU ----------------
__global__ void k_gxg(const float* __restrict__ gl_bih)
{
    int s = blockIdx.x >> 5;
    int b = blockIdx.x & 31;
    __shared__ float cx[W_];
    int t = threadIdx.x;             // 512
    if (t < W_) cx[t] = g_cx[(b*K_ + s)*W_ + t];
    __syncthreads();
    if (t < G_){
        float acc = gl_bih[t];
        #pragma unroll 4
        for (int i = 0; i < W_; i++) acc += cx[i] * g_glwihT[i*G_ + t];
        g_gxg[(s*B_ + b)*G_ + t] = acc;
    }
}

// ---------------- K4: global GRU (cluster 2, smem weights) ----------------
#define GL_W    0
#define GL_H0   33752
#define GL_H1   33912
#define GL_GH   34072
#define GL_BHH  34304
#define GL_SMEM_FLOATS (GL_BHH + 232)

__global__ __launch_bounds__(256, 1) __cluster_dims__(2,1,1)
void k_gru_gl(const float* __restrict__ gl_bhh)
{
    extern __shared__ __align__(16) float smg[];
    int b = blockIdx.x >> 1;
    unsigned hf = cta_rank();
    unsigned peer = hf ^ 1u;
    int t = threadIdx.x;             // 256

    float2* w2_sh  = (float2*)(smg + GL_W);
    float*  gh_sh  = smg + GL_GH;
    float*  bhh_sh = smg + GL_BHH;

    for (int e = t; e < 75*225; e += 256){
        int i2 = e / 225, c = e - i2*225;
        int gcol = (c/75)*H_ + (int)hf*75 + (c%75);
        w2_sh[e] = g_glwhhP[i2*G_ + gcol];
    }
    if (t < 225){
        int gcol = (t/75)*H_ + (int)hf*75 + (t%75);
        bhh_sh[t] = gl_bhh[gcol];
    }
    if (t < 152){ smg[GL_H0 + t] = 0.f; smg[GL_H1 + t] = 0.f; }
    cluster_sync();

    int cur = 0;
    for (int s = 0; s < 64; s++){
        float* h_cur = smg + (cur ? GL_H1 : GL_H0);
        float* h_nxt = smg + (cur ? GL_H0 : GL_H1);

        if (t < 225){
            unsigned long long acc = 0ull;
            const unsigned long long* hp = (const unsigned long long*)h_cur;
            const float2* wc = w2_sh + t;
            #pragma unroll 5
            for (int i2 = 0; i2 < 75; i2++){
                unsigned long long w2 = *(const unsigned long long*)(wc + i2*225);
                fma2(acc, w2, hp[i2]);
            }
            float2 v = up2(acc);
            gh_sh[t] = v.x + v.y + bhh_sh[t];
        }
        __syncthreads();

        if (t < 75){
            int j = (int)hf*75 + t;
            const float* gx = g_gxg + (s*B_ + b)*G_;
            float r  = sigf(gx[j]        + gh_sh[t]);
            float zz = sigf(gx[H_ + j]   + gh_sh[75 + t]);
            float n  = tanhf_(gx[2*H_+j] + r * gh_sh[150 + t]);
            float hnew = (1.f - zz)*n + zz*h_cur[j];
            h_nxt[j] = hnew;
            st_peer_f32(&h_nxt[j], peer, hnew);
        }
        cluster_sync();
        cur ^= 1;
    }
    float* hfin = smg + (cur ? GL_H1 : GL_H0);
    if (t < 75){
        int j = (int)hf*75 + t;
        g_hl[b*H_ + j] = hfin[j];
    }
}

// ---------------- K5: z ----------------
__global__ void k_z(const float* __restrict__ mu_b, const float* __restrict__ std_b,
                    const float* __restrict__ z_noise)
{
    int b = blockIdx.x, t = threadIdx.x;   // 160
    __shared__ float hs[152];
    if (t < H_) hs[t] = g_hl[b*H_ + t];
    __syncthreads();
    if (t < H_){
        float mu = mu_b[t], lv = std_b[t];
        #pragma unroll 2
        for (int i = 0; i < H_; i++){
            float h = hs[i];
            mu += h * g_muT[i*H_ + t];
            lv += h * g_stdT[i*H_ + t];
        }
        g_z[b*H_ + t] = mu + __expf(0.5f*lv) * z_noise[b*H_ + t];
    }
}

// ---------------- K6: gxnet GEMM — reg-pipelined staging, mma-first reorder ----
// grid 256: k = bid>>2, q = bid&3 (512 rows). 32 iters of 16 rows.
// Order after bar: mma(it) issues first; out(it-1) runs in HMMA shadow; epi last.
#define GXM_GH0  0
#define GXM_GH1  9216
#define GXM_BUF  18432
#define GXM_BI   21312
#define GXM_SMEM_FLOATS 21768

__global__ __launch_bounds__(512, 1)
void k_gxnet(const float* __restrict__ net_wih, const float* __restrict__ net_bih)
{
    extern __shared__ __align__(16) float sm6[];
    float*  gh0   = sm6 + GXM_GH0;
    float*  gh1   = sm6 + GXM_GH1;
    __half* bufs  = (__half*)(sm6 + GXM_BUF);  // 3 x [16][120]
    float*  bi_sh = sm6 + GXM_BI;

    int k = blockIdx.x >> 2;
    int q = blockIdx.x & 3;
    int t = threadIdx.x;             // 512
    int w = t >> 5, l = t & 31;
    int g = l >> 2, tg = l & 3;

    // ---- resident W fragments (fp16), built once ----
    unsigned Af[2][7][4];
    const float* wsrc = net_wih + k*(G_*W_);
    #pragma unroll
    for (int tile = 0; tile < 2; tile++){
        int mt = tile ? (w + 16) : w;
        #pragma unroll
        for (int kc = 0; kc < 7; kc++){
            #pragma unroll
            for (int qq = 0; qq < 4; qq++){
                int m = mt*16 + g + ((qq & 1) ? 8 : 0);
                int i = kc*16 + 2*tg + ((qq >= 2) ? 8 : 0);
                unsigned val = 0u;
                if (m < G_ && i < W_){
                    float2 f = *(const float2*)&wsrc[m*W_ + i];
                    __half2 h2 = __floats2half2_rn(f.x, f.y);
                    val = *(unsigned*)&h2;
                }
                Af[tile][kc][qq] = val;
            }
        }
    }

    if (t < 452) bi_sh[t] = (t < G_) ? net_bih[k*G_ + t] : 0.f;
    // zero k-pads of all 3 buffers
    for (int e = t; e < 480; e += 512){
        int bsel = e / 160, ee = e % 160;
        int rp = ee / 10, c2 = ee % 10;
        *(__half2*)&bufs[bsel*1920 + rp*120 + 100 + 2*c2] = __floats2half2_rn(0.f, 0.f);
    }

    int r0 = q*512;

    // ---- prologue: block0 -> regs -> buf0; block1 -> regs ----
    float2 pfA0, pfA1, pfB0, pfB1;
    pfA1.x = 0.f; pfA1.y = 0.f; pfB1.x = 0.f; pfB1.y = 0.f;
    {
        const float* Ab = g_Wx + r0*W_;
        { int rp = t / 50, ip = t % 50;
          if (t < 800) pfA0 = *(const float2*)&Ab[rp*W_ + 2*ip]; else {pfA0.x=0.f;pfA0.y=0.f;} }
        { int e = t + 512; int rp = e / 50, ip = e % 50;
          if (e < 800) pfA1 = *(const float2*)&Ab[rp*W_ + 2*ip]; }
        { int rp = t / 50, ip = t % 50;
          if (t < 800) *(__half2*)&bufs[rp*120 + 2*ip] = __floats2half2_rn(pfA0.x, pfA0.y); }
        { int e = t + 512; int rp = e / 50, ip = e % 50;
          if (e < 800) *(__half2*)&bufs[rp*120 + 2*ip] = __floats2half2_rn(pfA1.x, pfA1.y); }
        const float* Ab1p = g_Wx + (r0 + 16)*W_;
        { int rp = t / 50, ip = t % 50;
          if (t < 800) pfA0 = *(const float2*)&Ab1p[rp*W_ + 2*ip]; }
        { int e = t + 512; int rp = e / 50, ip = e % 50;
          if (e < 800) pfA1 = *(const float2*)&Ab1p[rp*W_ + 2*ip]; }
    }

    float c[2][2][4];

    for (int it = 0; it < 32; it++){
        __half* bcur = bufs + (it % 3)*1920;
        float*  gcur = (it & 1) ? gh1 : gh0;

        // issue LDG for block it+2 into pfB (consumed next iter)
        if (it < 30){
            const float* Ab = g_Wx + (r0 + (it + 2)*16)*W_;
            { int rp = t / 50, ip = t % 50;
              if (t < 800) pfB0 = *(const float2*)&Ab[rp*W_ + 2*ip]; }
            { int e = t + 512; int rp = e / 50, ip = e % 50;
              if (e < 800) pfB1 = *(const float2*)&Ab[rp*W_ + 2*ip]; }
        }
        // STS block it+1 from pfA regs (LDG issued one iter ago -> latency hidden)
        if (it < 31){
            __half* bnxt = bufs + ((it + 1) % 3)*1920;
            { int rp = t / 50, ip = t % 50;
              if (t < 800) *(__half2*)&bnxt[rp*120 + 2*ip] = __floats2half2_rn(pfA0.x, pfA0.y); }
            { int e = t + 512; int rp = e / 50, ip = e % 50;
              if (e < 800) *(__half2*)&bnxt[rp*120 + 2*ip] = __floats2half2_rn(pfA1.x, pfA1.y); }
        }
        __syncthreads();

        // ---- mma FIRST: HMMA issues immediately at bar release ----
        #pragma unroll
        for (int x1 = 0; x1 < 2; x1++)
            #pragma unroll
            for (int x2 = 0; x2 < 2; x2++)
                #pragma unroll
                for (int x3 = 0; x3 < 4; x3++) c[x1][x2][x3] = 0.f;

        const __half* hr0 = bcur + g*120 + 2*tg;
        const __half* hr1 = hr0 + 8*120;
        #pragma unroll
        for (int kc = 0; kc < 7; kc++){
            unsigned b00 = *(const unsigned*)&hr0[kc*16];
            unsigned b01 = *(const unsigned*)&hr0[kc*16 + 8];
            unsigned b10 = *(const unsigned*)&hr1[kc*16];
            unsigned b11 = *(const unsigned*)&hr1[kc*16 + 8];
            mma16816(c[0][0], Af[0][kc], b00, b01);
            mma16816(c[0][1], Af[0][kc], b10, b11);
            mma16816(c[1][0], Af[1][kc], b00, b01);
            mma16816(c[1][1], Af[1][kc], b10, b11);
        }

        // ---- out(it-1) in HMMA shadow (reads gprev, independent of mma) ----
        if (it > 0){
            float* gprev = (it & 1) ? gh0 : gh1;
            int rprev = r0 + (it - 1)*16;
            for (int e = t; e < 3600; e += 512){
                int rr = e / 225, mp = e % 225;
                int m0 = 2*mp;
                float v0 = gprev[m0*18 + rr]       + bi_sh[m0];
                float v1 = gprev[(m0 + 1)*18 + rr] + bi_sh[m0 + 1];
                int r = rprev + rr;
                long long o = (long long)(k*2048 + (r & 63)*B_ + (r >> 6))*G_ + m0;
                *(__half2*)&g_gxnet_h[o] = __floats2half2_rn(v0, v1);
            }
        }

        // ---- epi: waits on accumulators ----
        #pragma unroll
        for (int tile = 0; tile < 2; tile++){
            int m0 = (tile ? (w + 16) : w)*16 + g;
            #pragma unroll
            for (int nt = 0; nt < 2; nt++){
                int col = nt*8 + 2*tg;
                *(float2*)&gcur[(m0    )*18 + col] = make_float2(c[tile][nt][0], c[tile][nt][1]);
                *(float2*)&gcur[(m0 + 8)*18 + col] = make_float2(c[tile][nt][2], c[tile][nt][3]);
            }
        }

        pfA0 = pfB0; pfA1 = pfB1;
    }

    __syncthreads();
    // final output (it=31 wrote gh1)
    {
        int rprev = r0 + 31*16;
        for (int e = t; e < 3600; e += 512){
            int rr = e / 225, mp = e % 225;
            int m0 = 2*mp;
            float v0 = gh1[m0*18 + rr]       + bi_sh[m0];
            float v1 = gh1[(m0 + 1)*18 + rr] + bi_sh[m0 + 1];
            int r = rprev + rr;
            long long o = (long long)(k*2048 + (r & 63)*B_ + (r >> 6))*G_ + m0;
            *(__half2*)&g_gxnet_h[o] = __floats2half2_rn(v0, v1);
        }
    }
}

// ---------------- K7: net GRUs — mma.sync + gx prefetch + tanh.approx (R10/R14)
#define GRN_GHO  0                    // gh fp32 [512][18]
#define GRN_HO   9216                 // h  fp32 [150][18]
#define GRN_HTO  11916                // hT fp16 [16][168]
#define GRN_BHO  13260                // bhh fp32 [452]
#define GRN_SMEM_FLOATS (13260 + 452)

__global__ __launch_bounds__(512, 1)
void k_gru_net(const float* __restrict__ net_whh, const float* __restrict__ net_bhh,
               float* __restrict__ out)
{
    extern __shared__ __align__(16) float sm7[];
    float*  gh_sh  = sm7 + GRN_GHO;
    float*  h_sh   = sm7 + GRN_HO;
    __half* hT     = (__half*)(sm7 + GRN_HTO);
    float*  bhh_sh = sm7 + GRN_BHO;

    int k  = blockIdx.x >> 1;
    int b0 = (blockIdx.x & 1) * 16;
    int t  = threadIdx.x;             // 512
    int w  = t >> 5, l = t & 31;
    int g  = l >> 2, tg = l & 3;

    unsigned Af[2][10][4];
    const float* wsrc = net_whh + k*(G_*H_);
    #pragma unroll
    for (int tile = 0; tile < 2; tile++){
        int mt = tile ? (w + 16) : w;
        #pragma unroll
        for (int kc = 0; kc < 10; kc++){
            #pragma unroll
            for (int qq = 0; qq < 4; qq++){
                int m = mt*16 + g + ((qq & 1) ? 8 : 0);
                int i = kc*16 + 2*tg + ((qq >= 2) ? 8 : 0);
                unsigned val = 0u;
                if (m < G_ && i < H_){
                    float2 f = *(const float2*)&wsrc[m*H_ + i];
                    __half2 h2 = __floats2half2_rn(f.x, f.y);
                    val = *(unsigned*)&h2;
                }
                Af[tile][kc][qq] = val;
            }
        }
    }

    for (int e = t; e < H_*16; e += 512){
        int j = e % H_, bb = e / H_;
        float hv = g_z[(b0 + bb)*H_ + j];
        h_sh[j*18 + bb] = hv;
        hT[bb*168 + j] = __float2half(hv);
    }
    for (int e = t; e < 16*18; e += 512){
        int bb = e / 18, c = e % 18;
        hT[bb*168 + 150 + c] = __half(0.f);
    }
    if (t < 452) bhh_sh[t] = (t < G_) ? net_bhh[k*G_ + t] : 0.f;
    __syncthreads();

    const __half* gxk = g_gxnet_h + (long long)k*2048*G_;

    for (int s = 0; s < 64; s++){
        float pgx[3][6];
        #pragma unroll
        for (int u = 0; u < 3; u++){
            int e = t + u*512;
            if (e < 1200){
                int j = e % H_, bp = e / H_;
                const __half* gx0 = gxk + (long long)(s*B_ + b0 + 2*bp)*G_ + j;
                pgx[u][0] = __half2float(gx0[0]);
                pgx[u][1] = __half2float(gx0[H_]);
                pgx[u][2] = __half2float(gx0[2*H_]);
                pgx[u][3] = __half2float(gx0[G_]);
                pgx[u][4] = __half2float(gx0[G_ + H_]);
                pgx[u][5] = __half2float(gx0[G_ + 2*H_]);
            }
        }

        float c[2][2][4];
        #pragma unroll
        for (int x1 = 0; x1 < 2; x1++)
            #pragma unroll
            for (int x2 = 0; x2 < 2; x2++)
                #pragma unroll
                for (int x3 = 0; x3 < 4; x3++) c[x1][x2][x3] = 0.f;

        const __half* hr0 = hT + g*168 + 2*tg;
        const __half* hr1 = hr0 + 8*168;
        #pragma unroll
        for (int kc = 0; kc < 10; kc++){
            unsigned b00 = *(const unsigned*)&hr0[kc*16];
            unsigned b01 = *(const unsigned*)&hr0[kc*16 + 8];
            unsigned b10 = *(const unsigned*)&hr1[kc*16];
            unsigned b11 = *(const unsigned*)&hr1[kc*16 + 8];
            mma16816(c[0][0], Af[0][kc], b00, b01);
            mma16816(c[0][1], Af[0][kc], b10, b11);
            mma16816(c[1][0], Af[1][kc], b00, b01);
            mma16816(c[1][1], Af[1][kc], b10, b11);
        }

        #pragma unroll
        for (int tile = 0; tile < 2; tile++){
            int m0 = (tile ? (w + 16) : w)*16 + g;
            #pragma unroll
            for (int nt = 0; nt < 2; nt++){
                int col = nt*8 + 2*tg;
                *(float2*)&gh_sh[(m0    )*18 + col] = make_float2(c[tile][nt][0], c[tile][nt][1]);
                *(float2*)&gh_sh[(m0 + 8)*18 + col] = make_float2(c[tile][nt][2], c[tile][nt][3]);
            }
        }
        __syncthreads();

        #pragma unroll
        for (int u = 0; u < 3; u++){
            int e = t + u*512;
            if (e < 1200){
                int j = e % H_, bp = e / H_;
                int bb0 = 2*bp, bb1 = bb0 + 1;
                float bhr = bhh_sh[j];
                float bhz = bhh_sh[H_ + j];
                float bhn = bhh_sh[2*H_ + j];
                float ghr0 = gh_sh[(j       )*18 + bb0] + bhr;
                float ghz0 = gh_sh[(H_  + j )*18 + bb0] + bhz;
                float ghn0 = gh_sh[(2*H_+ j )*18 + bb0] + bhn;
                float ghr1 = gh_sh[(j       )*18 + bb1] + bhr;
                float ghz1 = gh_sh[(H_  + j )*18 + bb1] + bhz;
                float ghn1 = gh_sh[(2*H_+ j )*18 + bb1] + bhn;
                float r0  = siga(pgx[u][0] + ghr0);
                float zz0 = siga(pgx[u][1] + ghz0);
                float n0  = tanha(pgx[u][2] + r0*ghn0);
                float r1  = siga(pgx[u][3] + ghr1);
                float zz1 = siga(pgx[u][4] + ghz1);
                float n1  = tanha(pgx[u][5] + r1*ghn1);
                float h0o = h_sh[j*18 + bb0];
                float h1o = h_sh[j*18 + bb1];
                float hn0 = (1.f - zz0)*n0 + zz0*h0o;
                float hn1 = (1.f - zz1)*n1 + zz1*h1o;
                h_sh[j*18 + bb0] = hn0;
                h_sh[j*18 + bb1] = hn1;
                hT[bb0*168 + j] = __float2half(hn0);
                hT[bb1*168 + j] = __float2half(hn1);
            }
        }
        __syncthreads();
    }

    for (int e = t; e < H_*16; e += 512){
        int j = e % H_, bb = e / H_;
        out[(b0 + bb)*(K_*H_) + k*H_ + j] = h_sh[j*18 + bb];
    }
}

// ---------------- launch (R10/R14 schedule) ----------------
extern "C" void kernel_launch(void* const* d_in, const int* in_sizes, int n_in,
                              void* d_out, int out_size)
{
    const float* x       = (const float*)d_in[0];
    const float* y       = (const float*)d_in[1];
    const float* z_noise = (const float*)d_in[2];
    const float* lin_w   = (const float*)d_in[3];
    const float* lin_b   = (const float*)d_in[4];
    const float* a       = (const float*)d_in[5];
    const float* bias    = (const float*)d_in[6];
    const float* gl_wih  = (const float*)d_in[7];
    const float* gl_whh  = (const float*)d_in[8];
    const float* gl_bih  = (const float*)d_in[9];
    const float* gl_bhh  = (const float*)d_in[10];
    const float* mu_w    = (const float*)d_in[11];
    const float* mu_b    = (const float*)d_in[12];
    const float* std_w   = (const float*)d_in[13];
    const float* std_b   = (const float*)d_in[14];
    const float* net_wih = (const float*)d_in[15];
    const float* net_whh = (const float*)d_in[16];
    const float* net_bih = (const float*)d_in[17];
    const float* net_bhh = (const float*)d_in[18];
    float* out = (float*)d_out;

    static cudaStream_t s_side = nullptr;
    static cudaEvent_t ev1 = nullptr, ev2 = nullptr;
    if (!s_side){
        cudaStreamCreateWithFlags(&s_side, cudaStreamNonBlocking);
        cudaEventCreateWithFlags(&ev1, cudaEventDisableTiming);
        cudaEventCreateWithFlags(&ev2, cudaEventDisableTiming);
        cudaFuncSetAttribute(k_gxnet,   cudaFuncAttributeMaxDynamicSharedMemorySize,
                             GXM_SMEM_FLOATS*4);
        cudaFuncSetAttribute(k_gru_net, cudaFuncAttributeMaxDynamicSharedMemorySize,
                             GRN_SMEM_FLOATS*4);
        cudaFuncSetAttribute(k_gru_gl,  cudaFuncAttributeMaxDynamicSharedMemorySize,
                             GL_SMEM_FLOATS*4);
    }

    k_prep<<<256, 256, 0, s_side>>>(gl_wih, gl_whh, mu_w, std_w);

    k_wx<<<B_*K_, 128>>>(x, lin_w, lin_b);
    cudaEventRecord(ev1, 0);

    k_gxnet<<<K_*4, 512, GXM_SMEM_FLOATS*4>>>(net_wih, net_bih);

    cudaStreamWaitEvent(s_side, ev1, 0);
    k_attn<<<B_*K_, 256, 0, s_side>>>(y, a, bias);
    k_gxg<<<K_*B_, 512, 0, s_side>>>(gl_bih);
    k_gru_gl<<<B_*2, 256, GL_SMEM_FLOATS*4, s_side>>>(gl_bhh);
    k_z<<<B_, 160, 0, s_side>>>(mu_b, std_b, z_noise);
    cudaEventRecord(ev2, s_side);

    cudaStreamWaitEvent(0, ev2, 0);
    k_gru_net<<<K_*2, 512, GRN_SMEM_FLOATS*4>>>(net_whh, net_bhh, out);
}

// round 17
// speedup vs baseline: 1.0472x; 1.0134x over previous
#include <cuda_runtime.h>
#include <cuda_fp16.h>

#define B_ 32
#define K_ 64
#define W_ 100
#define H_ 150
#define G_ 450
#define KW_ 6400
#define ALPHA_ 0.2f
#define THRES_ 0.0002f

// ---------------- scratch ----------------
__device__ float g_Wx[B_*K_*W_];
__device__ float g_cx[B_*K_*W_];
__device__ float g_glwihT[W_*G_];
__device__ float2 g_glwhhP[(H_/2)*G_];
__device__ float g_muT[H_*H_];
__device__ float g_stdT[H_*H_];
__device__ float g_gxg[K_*B_*G_];
__device__ float g_hl[B_*H_];
__device__ float g_z[B_*H_];
__device__ __half g_gxnet_h[K_*B_*K_*G_];        // [k][s][b][g]

// ---------------- helpers ----------------
__device__ __forceinline__ unsigned long long pk2(float a, float b){
    unsigned long long r;
    asm("mov.b64 %0, {%1,%2};" : "=l"(r) : "f"(a), "f"(b));
    return r;
}
__device__ __forceinline__ void fma2(unsigned long long &d, unsigned long long a, unsigned long long b){
    asm("fma.rn.f32x2 %0, %1, %2, %0;" : "+l"(d) : "l"(a), "l"(b));
}
__device__ __forceinline__ float2 up2(unsigned long long v){
    float a, b;
    asm("mov.b64 {%0,%1}, %2;" : "=f"(a), "=f"(b) : "l"(v));
    float2 r; r.x = a; r.y = b; return r;
}
__device__ __forceinline__ float sigf(float x){ return __fdividef(1.f, 1.f + __expf(-x)); }
__device__ __forceinline__ float tanhf_(float x){
    float e = __expf(2.f * x);
    return 1.f - __fdividef(2.f, e + 1.f);
}
__device__ __forceinline__ float tanha(float x){
    float r; asm("tanh.approx.f32 %0, %1;" : "=f"(r) : "f"(x)); return r;
}
__device__ __forceinline__ float siga(float x){ return fmaf(0.5f, tanha(0.5f*x), 0.5f); }
// two sigmoids in one MUFU op: sig(x) = 0.5*tanh(0.5x)+0.5, tanh via f16x2
__device__ __forceinline__ float2 siga2(float x0, float x1){
    __half2 hx = __floats2half2_rn(0.5f*x0, 0.5f*x1);
    unsigned u = *(unsigned*)&hx;
    asm("tanh.approx.f16x2 %0, %0;" : "+r"(u));
    __half2 ht = *(__half2*)&u;
    float2 f = __half22float2(ht);
    f.x = fmaf(0.5f, f.x, 0.5f);
    f.y = fmaf(0.5f, f.y, 0.5f);
    return f;
}
__device__ __forceinline__ unsigned cta_rank(){
    unsigned r; asm("mov.u32 %0, %%cluster_ctarank;" : "=r"(r)); return r;
}
__device__ __forceinline__ void cluster_sync(){
    asm volatile("barrier.cluster.arrive.aligned;" ::: "memory");
    asm volatile("barrier.cluster.wait.aligned;"  ::: "memory");
}
__device__ __forceinline__ void st_peer_f32(float* local_ptr, unsigned peer, float v){
    unsigned la = (unsigned)__cvta_generic_to_shared(local_ptr);
    unsigned ra;
    asm volatile("mapa.shared::cluster.u32 %0, %1, %2;" : "=r"(ra) : "r"(la), "r"(peer));
    asm volatile("st.shared::cluster.f32 [%0], %1;" :: "r"(ra), "f"(v) : "memory");
}
__device__ __forceinline__ void mma16816(float* c, const unsigned* a, unsigned b0, unsigned b1){
    asm volatile("mma.sync.aligned.m16n8k16.row.col.f32.f16.f16.f32 "
        "{%0,%1,%2,%3}, {%4,%5,%6,%7}, {%8,%9}, {%0,%1,%2,%3};"
        : "+f"(c[0]), "+f"(c[1]), "+f"(c[2]), "+f"(c[3])
        : "r"(a[0]), "r"(a[1]), "r"(a[2]), "r"(a[3]), "r"(b0), "r"(b1));
}

// ---------------- prep (side stream) ----------------
__global__ void k_prep(const float* gl_wih, const float* gl_whh,
                       const float* mu_w, const float* std_w)
{
    int tid = blockIdx.x * blockDim.x + threadIdx.x;
    int stride = gridDim.x * blockDim.x;
    for (int e = tid; e < G_*W_; e += stride){
        int g = e / W_, i = e % W_;
        g_glwihT[i*G_ + g] = gl_wih[e];
    }
    for (int e = tid; e < (H_/2)*G_; e += stride){
        int i2 = e / G_, g = e % G_;
        float2 v;
        v.x = gl_whh[g*H_ + 2*i2];
        v.y = gl_whh[g*H_ + 2*i2 + 1];
        g_glwhhP[e] = v;
    }
    for (int e = tid; e < H_*H_; e += stride){
        int o = e / H_, i = e % H_;
        g_muT[i*H_ + o]  = mu_w[e];
        g_stdT[i*H_ + o] = std_w[e];
    }
}

// ---------------- K1: Wx ----------------
__global__ void k_wx(const float* __restrict__ x, const float* __restrict__ lin_w,
                     const float* __restrict__ lin_b)
{
    __shared__ float xs[W_];
    int row = blockIdx.x;
    int t = threadIdx.x;
    if (t < W_) xs[t] = x[row*W_ + t];
    __syncthreads();
    if (t < W_){
        float acc = lin_b[t];
        const float* lw = lin_w + t*W_;
        #pragma unroll 4
        for (int i = 0; i < W_; i++) acc += xs[i] * lw[i];
        g_Wx[row*W_ + t] = acc;
    }
}

// ---------------- K2: attention ----------------
__global__ __launch_bounds__(256) void k_attn(const float* __restrict__ y,
                       const float* __restrict__ a, const float* __restrict__ bias)
{
    int b = blockIdx.x >> 6;
    int k = blockIdx.x & 63;
    const float a0 = a[0], a1 = a[1];
    const float yb = a0 * y[b*K_ + k];
    const float* vrow = g_Wx + b*KW_;
    const float* brow = bias + k*KW_;
    int t = threadIdx.x;             // 256

    __shared__ float red[256];

    float e_loc[25], v_loc[25];
    float m = -3.4e38f;
    #pragma unroll
    for (int jj = 0; jj < 25; jj++){
        int j = t + jj*256;
        float v = vrow[j];
        float e = yb + a1*v + brow[j];
        e = e > 0.f ? e : ALPHA_*e;
        e_loc[jj] = e; v_loc[jj] = v;
        m = fmaxf(m, e);
    }
    red[t] = m; __syncthreads();
    for (int o = 128; o > 0; o >>= 1){
        if (t < o) red[t] = fmaxf(red[t], red[t+o]);
        __syncthreads();
    }
    float M = red[0]; __syncthreads();

    float ssum = 0.f;
    #pragma unroll
    for (int jj = 0; jj < 25; jj++) ssum += __expf(e_loc[jj] - M);
    red[t] = ssum; __syncthreads();
    for (int o = 128; o > 0; o >>= 1){
        if (t < o) red[t] += red[t+o];
        __syncthreads();
    }
    float S = red[0]; __syncthreads();

    float T = M + __logf(THRES_ * S);

    float acc = 0.f;
    #pragma unroll
    for (int jj = 0; jj < 25; jj++) if (e_loc[jj] >= T) acc += v_loc[jj];
    red[t] = acc; __syncthreads();
    for (int o = 128; o > 0; o >>= 1){
        if (t < o) red[t] += red[t+o];
        __syncthreads();
    }
    float sbk = red[0];

    if (t < W_){
        int row = b*K_ + k;
        g_cx[row*W_ + t] = g_Wx[row*W_ + t] + sbk;
    }
}

// ---------------- K3: gx for global GRU ----------------
__global__ void k_gxg(const float* __restrict__ gl_bih)
{
    int s = blockIdx.x >> 5;
    int b = blockIdx.x & 31;
    __shared__ float cx[W_];
    int t = threadIdx.x;             // 512
    if (t < W_) cx[t] = g_cx[(b*K_ + s)*W_ + t];
    __syncthreads();
    if (t < G_){
        float acc = gl_bih[t];
        #pragma unroll 4
        for (int i = 0; i < W_; i++) acc += cx[i] * g_glwihT[i*G_ + t];
        g_gxg[(s*B_ + b)*G_ + t] = acc;
    }
}

// ---------------- K4: global GRU (cluster 2, smem weights) ----------------
#define GL_W    0
#define GL_H0   33752
#define GL_H1   33912
#define GL_GH   34072
#define GL_BHH  34304
#define GL_SMEM_FLOATS (GL_BHH + 232)

__global__ __launch_bounds__(256, 1) __cluster_dims__(2,1,1)
void k_gru_gl(const float* __restrict__ gl_bhh)
{
    extern __shared__ __align__(16) float smg[];
    int b = blockIdx.x >> 1;
    unsigned hf = cta_rank();
    unsigned peer = hf ^ 1u;
    int t = threadIdx.x;             // 256

    float2* w2_sh  = (float2*)(smg + GL_W);
    float*  gh_sh  = smg + GL_GH;
    float*  bhh_sh = smg + GL_BHH;

    for (int e = t; e < 75*225; e += 256){
        int i2 = e / 225, c = e - i2*225;
        int gcol = (c/75)*H_ + (int)hf*75 + (c%75);
        w2_sh[e] = g_glwhhP[i2*G_ + gcol];
    }
    if (t < 225){
        int gcol = (t/75)*H_ + (int)hf*75 + (t%75);
        bhh_sh[t] = gl_bhh[gcol];
    }
    if (t < 152){ smg[GL_H0 + t] = 0.f; smg[GL_H1 + t] = 0.f; }
    cluster_sync();

    int cur = 0;
    for (int s = 0; s < 64; s++){
        float* h_cur = smg + (cur ? GL_H1 : GL_H0);
        float* h_nxt = smg + (cur ? GL_H0 : GL_H1);

        if (t < 225){
            unsigned long long acc = 0ull;
            const unsigned long long* hp = (const unsigned long long*)h_cur;
            const float2* wc = w2_sh + t;
            #pragma unroll 5
            for (int i2 = 0; i2 < 75; i2++){
                unsigned long long w2 = *(const unsigned long long*)(wc + i2*225);
                fma2(acc, w2, hp[i2]);
            }
            float2 v = up2(acc);
            gh_sh[t] = v.x + v.y + bhh_sh[t];
        }
        __syncthreads();

        if (t < 75){
            int j = (int)hf*75 + t;
            const float* gx = g_gxg + (s*B_ + b)*G_;
            float r  = sigf(gx[j]        + gh_sh[t]);
            float zz = sigf(gx[H_ + j]   + gh_sh[75 + t]);
            float n  = tanhf_(gx[2*H_+j] + r * gh_sh[150 + t]);
            float hnew = (1.f - zz)*n + zz*h_cur[j];
            h_nxt[j] = hnew;
            st_peer_f32(&h_nxt[j], peer, hnew);
        }
        cluster_sync();
        cur ^= 1;
    }
    float* hfin = smg + (cur ? GL_H1 : GL_H0);
    if (t < 75){
        int j = (int)hf*75 + t;
        g_hl[b*H_ + j] = hfin[j];
    }
}

// ---------------- K5: z ----------------
__global__ void k_z(const float* __restrict__ mu_b, const float* __restrict__ std_b,
                    const float* __restrict__ z_noise)
{
    int b = blockIdx.x, t = threadIdx.x;   // 160
    __shared__ float hs[152];
    if (t < H_) hs[t] = g_hl[b*H_ + t];
    __syncthreads();
    if (t < H_){
        float mu = mu_b[t], lv = std_b[t];
        #pragma unroll 2
        for (int i = 0; i < H_; i++){
            float h = hs[i];
            mu += h * g_muT[i*H_ + t];
            lv += h * g_stdT[i*H_ + t];
        }
        g_z[b*H_ + t] = mu + __expf(0.5f*lv) * z_noise[b*H_ + t];
    }
}

// ---------------- K6: gxnet GEMM — R14 version (reg-pipelined 2-ahead staging) -
#define GXM_GH0  0
#define GXM_GH1  9216
#define GXM_BUF  18432
#define GXM_BI   21312
#define GXM_SMEM_FLOATS 21768

__global__ __launch_bounds__(512, 1)
void k_gxnet(const float* __restrict__ net_wih, const float* __restrict__ net_bih)
{
    extern __shared__ __align__(16) float sm6[];
    float*  gh0   = sm6 + GXM_GH0;
    float*  gh1   = sm6 + GXM_GH1;
    __half* bufs  = (__half*)(sm6 + GXM_BUF);  // 3 x [16][120]
    float*  bi_sh = sm6 + GXM_BI;

    int k = blockIdx.x >> 2;
    int q = blockIdx.x & 3;
    int t = threadIdx.x;             // 512
    int w = t >> 5, l = t & 31;
    int g = l >> 2, tg = l & 3;

    unsigned Af[2][7][4];
    const float* wsrc = net_wih + k*(G_*W_);
    #pragma unroll
    for (int tile = 0; tile < 2; tile++){
        int mt = tile ? (w + 16) : w;
        #pragma unroll
        for (int kc = 0; kc < 7; kc++){
            #pragma unroll
            for (int qq = 0; qq < 4; qq++){
                int m = mt*16 + g + ((qq & 1) ? 8 : 0);
                int i = kc*16 + 2*tg + ((qq >= 2) ? 8 : 0);
                unsigned val = 0u;
                if (m < G_ && i < W_){
                    float2 f = *(const float2*)&wsrc[m*W_ + i];
                    __half2 h2 = __floats2half2_rn(f.x, f.y);
                    val = *(unsigned*)&h2;
                }
                Af[tile][kc][qq] = val;
            }
        }
    }

    if (t < 452) bi_sh[t] = (t < G_) ? net_bih[k*G_ + t] : 0.f;
    for (int e = t; e < 480; e += 512){
        int bsel = e / 160, ee = e % 160;
        int rp = ee / 10, c2 = ee % 10;
        *(__half2*)&bufs[bsel*1920 + rp*120 + 100 + 2*c2] = __floats2half2_rn(0.f, 0.f);
    }

    int r0 = q*512;

    float2 pfA0, pfA1, pfB0, pfB1;
    pfA1.x = 0.f; pfA1.y = 0.f; pfB1.x = 0.f; pfB1.y = 0.f;
    {
        const float* Ab = g_Wx + r0*W_;
        { int rp = t / 50, ip = t % 50;
          if (t < 800) pfA0 = *(const float2*)&Ab[rp*W_ + 2*ip]; else {pfA0.x=0.f;pfA0.y=0.f;} }
        { int e = t + 512; int rp = e / 50, ip = e % 50;
          if (e < 800) pfA1 = *(const float2*)&Ab[rp*W_ + 2*ip]; }
        { int rp = t / 50, ip = t % 50;
          if (t < 800) *(__half2*)&bufs[rp*120 + 2*ip] = __floats2half2_rn(pfA0.x, pfA0.y); }
        { int e = t + 512; int rp = e / 50, ip = e % 50;
          if (e < 800) *(__half2*)&bufs[rp*120 + 2*ip] = __floats2half2_rn(pfA1.x, pfA1.y); }
        const float* Ab1p = g_Wx + (r0 + 16)*W_;
        { int rp = t / 50, ip = t % 50;
          if (t < 800) pfA0 = *(const float2*)&Ab1p[rp*W_ + 2*ip]; }
        { int e = t + 512; int rp = e / 50, ip = e % 50;
          if (e < 800) pfA1 = *(const float2*)&Ab1p[rp*W_ + 2*ip]; }
    }

    float c[2][2][4];

    for (int it = 0; it < 32; it++){
        __half* bcur = bufs + (it % 3)*1920;
        float*  gcur = (it & 1) ? gh1 : gh0;

        if (it < 30){
            const float* Ab = g_Wx + (r0 + (it + 2)*16)*W_;
            { int rp = t / 50, ip = t % 50;
              if (t < 800) pfB0 = *(const float2*)&Ab[rp*W_ + 2*ip]; }
            { int e = t + 512; int rp = e / 50, ip = e % 50;
              if (e < 800) pfB1 = *(const float2*)&Ab[rp*W_ + 2*ip]; }
        }
        if (it < 31){
            __half* bnxt = bufs + ((it + 1) % 3)*1920;
            { int rp = t / 50, ip = t % 50;
              if (t < 800) *(__half2*)&bnxt[rp*120 + 2*ip] = __floats2half2_rn(pfA0.x, pfA0.y); }
            { int e = t + 512; int rp = e / 50, ip = e % 50;
              if (e < 800) *(__half2*)&bnxt[rp*120 + 2*ip] = __floats2half2_rn(pfA1.x, pfA1.y); }
        }
        __syncthreads();

        if (it > 0){
            float* gprev = (it & 1) ? gh0 : gh1;
            int rprev = r0 + (it - 1)*16;
            for (int e = t; e < 3600; e += 512){
                int rr = e / 225, mp = e % 225;
                int m0 = 2*mp;
                float v0 = gprev[m0*18 + rr]       + bi_sh[m0];
                float v1 = gprev[(m0 + 1)*18 + rr] + bi_sh[m0 + 1];
                int r = rprev + rr;
                long long o = (long long)(k*2048 + (r & 63)*B_ + (r >> 6))*G_ + m0;
                *(__half2*)&g_gxnet_h[o] = __floats2half2_rn(v0, v1);
            }
        }

        #pragma unroll
        for (int x1 = 0; x1 < 2; x1++)
            #pragma unroll
            for (int x2 = 0; x2 < 2; x2++)
                #pragma unroll
                for (int x3 = 0; x3 < 4; x3++) c[x1][x2][x3] = 0.f;

        const __half* hr0 = bcur + g*120 + 2*tg;
        const __half* hr1 = hr0 + 8*120;
        #pragma unroll
        for (int kc = 0; kc < 7; kc++){
            unsigned b00 = *(const unsigned*)&hr0[kc*16];
            unsigned b01 = *(const unsigned*)&hr0[kc*16 + 8];
            unsigned b10 = *(const unsigned*)&hr1[kc*16];
            unsigned b11 = *(const unsigned*)&hr1[kc*16 + 8];
            mma16816(c[0][0], Af[0][kc], b00, b01);
            mma16816(c[0][1], Af[0][kc], b10, b11);
            mma16816(c[1][0], Af[1][kc], b00, b01);
            mma16816(c[1][1], Af[1][kc], b10, b11);
        }

        #pragma unroll
        for (int tile = 0; tile < 2; tile++){
            int m0 = (tile ? (w + 16) : w)*16 + g;
            #pragma unroll
            for (int nt = 0; nt < 2; nt++){
                int col = nt*8 + 2*tg;
                *(float2*)&gcur[(m0    )*18 + col] = make_float2(c[tile][nt][0], c[tile][nt][1]);
                *(float2*)&gcur[(m0 + 8)*18 + col] = make_float2(c[tile][nt][2], c[tile][nt][3]);
            }
        }

        pfA0 = pfB0; pfA1 = pfB1;
    }

    __syncthreads();
    {
        int rprev = r0 + 31*16;
        for (int e = t; e < 3600; e += 512){
            int rr = e / 225, mp = e % 225;
            int m0 = 2*mp;
            float v0 = gh1[m0*18 + rr]       + bi_sh[m0];
            float v1 = gh1[(m0 + 1)*18 + rr] + bi_sh[m0 + 1];
            int r = rprev + rr;
            long long o = (long long)(k*2048 + (r & 63)*B_ + (r >> 6))*G_ + m0;
            *(__half2*)&g_gxnet_h[o] = __floats2half2_rn(v0, v1);
        }
    }
}

// ---------------- K7: net GRUs — R14 + f16x2 sigmoids (r,z), fp32 tanh (n) -----
#define GRN_GHO  0                    // gh fp32 [512][18]
#define GRN_HO   9216                 // h  fp32 [150][18]
#define GRN_HTO  11916                // hT fp16 [16][168]
#define GRN_BHO  13260                // bhh fp32 [452]
#define GRN_SMEM_FLOATS (13260 + 452)

__global__ __launch_bounds__(512, 1)
void k_gru_net(const float* __restrict__ net_whh, const float* __restrict__ net_bhh,
               float* __restrict__ out)
{
    extern __shared__ __align__(16) float sm7[];
    float*  gh_sh  = sm7 + GRN_GHO;
    float*  h_sh   = sm7 + GRN_HO;
    __half* hT     = (__half*)(sm7 + GRN_HTO);
    float*  bhh_sh = sm7 + GRN_BHO;

    int k  = blockIdx.x >> 1;
    int b0 = (blockIdx.x & 1) * 16;
    int t  = threadIdx.x;             // 512
    int w  = t >> 5, l = t & 31;
    int g  = l >> 2, tg = l & 3;

    unsigned Af[2][10][4];
    const float* wsrc = net_whh + k*(G_*H_);
    #pragma unroll
    for (int tile = 0; tile < 2; tile++){
        int mt = tile ? (w + 16) : w;
        #pragma unroll
        for (int kc = 0; kc < 10; kc++){
            #pragma unroll
            for (int qq = 0; qq < 4; qq++){
                int m = mt*16 + g + ((qq & 1) ? 8 : 0);
                int i = kc*16 + 2*tg + ((qq >= 2) ? 8 : 0);
                unsigned val = 0u;
                if (m < G_ && i < H_){
                    float2 f = *(const float2*)&wsrc[m*H_ + i];
                    __half2 h2 = __floats2half2_rn(f.x, f.y);
                    val = *(unsigned*)&h2;
                }
                Af[tile][kc][qq] = val;
            }
        }
    }

    for (int e = t; e < H_*16; e += 512){
        int j = e % H_, bb = e / H_;
        float hv = g_z[(b0 + bb)*H_ + j];
        h_sh[j*18 + bb] = hv;
        hT[bb*168 + j] = __float2half(hv);
    }
    for (int e = t; e < 16*18; e += 512){
        int bb = e / 18, c = e % 18;
        hT[bb*168 + 150 + c] = __half(0.f);
    }
    if (t < 452) bhh_sh[t] = (t < G_) ? net_bhh[k*G_ + t] : 0.f;
    __syncthreads();

    const __half* gxk = g_gxnet_h + (long long)k*2048*G_;

    for (int s = 0; s < 64; s++){
        float pgx[3][6];
        #pragma unroll
        for (int u = 0; u < 3; u++){
            int e = t + u*512;
            if (e < 1200){
                int j = e % H_, bp = e / H_;
                const __half* gx0 = gxk + (long long)(s*B_ + b0 + 2*bp)*G_ + j;
                pgx[u][0] = __half2float(gx0[0]);
                pgx[u][1] = __half2float(gx0[H_]);
                pgx[u][2] = __half2float(gx0[2*H_]);
                pgx[u][3] = __half2float(gx0[G_]);
                pgx[u][4] = __half2float(gx0[G_ + H_]);
                pgx[u][5] = __half2float(gx0[G_ + 2*H_]);
            }
        }

        float c[2][2][4];
        #pragma unroll
        for (int x1 = 0; x1 < 2; x1++)
            #pragma unroll
            for (int x2 = 0; x2 < 2; x2++)
                #pragma unroll
                for (int x3 = 0; x3 < 4; x3++) c[x1][x2][x3] = 0.f;

        const __half* hr0 = hT + g*168 + 2*tg;
        const __half* hr1 = hr0 + 8*168;
        #pragma unroll
        for (int kc = 0; kc < 10; kc++){
            unsigned b00 = *(const unsigned*)&hr0[kc*16];
            unsigned b01 = *(const unsigned*)&hr0[kc*16 + 8];
            unsigned b10 = *(const unsigned*)&hr1[kc*16];
            unsigned b11 = *(const unsigned*)&hr1[kc*16 + 8];
            mma16816(c[0][0], Af[0][kc], b00, b01);
            mma16816(c[0][1], Af[0][kc], b10, b11);
            mma16816(c[1][0], Af[1][kc], b00, b01);
            mma16816(c[1][1], Af[1][kc], b10, b11);
        }

        #pragma unroll
        for (int tile = 0; tile < 2; tile++){
            int m0 = (tile ? (w + 16) : w)*16 + g;
            #pragma unroll
            for (int nt = 0; nt < 2; nt++){
                int col = nt*8 + 2*tg;
                *(float2*)&gh_sh[(m0    )*18 + col] = make_float2(c[tile][nt][0], c[tile][nt][1]);
                *(float2*)&gh_sh[(m0 + 8)*18 + col] = make_float2(c[tile][nt][2], c[tile][nt][3]);
            }
        }
        __syncthreads();

        #pragma unroll
        for (int u = 0; u < 3; u++){
            int e = t + u*512;
            if (e < 1200){
                int j = e % H_, bp = e / H_;
                int bb0 = 2*bp, bb1 = bb0 + 1;
                float bhr = bhh_sh[j];
                float bhz = bhh_sh[H_ + j];
                float bhn = bhh_sh[2*H_ + j];
                float ghr0 = gh_sh[(j       )*18 + bb0] + bhr;
                float ghz0 = gh_sh[(H_  + j )*18 + bb0] + bhz;
                float ghn0 = gh_sh[(2*H_+ j )*18 + bb0] + bhn;
                float ghr1 = gh_sh[(j       )*18 + bb1] + bhr;
                float ghz1 = gh_sh[(H_  + j )*18 + bb1] + bhz;
                float ghn1 = gh_sh[(2*H_+ j )*18 + bb1] + bhn;
                // r gates for both batches in one MUFU; z likewise
                float2 rr = siga2(pgx[u][0] + ghr0, pgx[u][3] + ghr1);
                float2 zz = siga2(pgx[u][1] + ghz0, pgx[u][4] + ghz1);
                float n0  = tanha(pgx[u][2] + rr.x*ghn0);
                float n1  = tanha(pgx[u][5] + rr.y*ghn1);
                float h0o = h_sh[j*18 + bb0];
                float h1o = h_sh[j*18 + bb1];
                float hn0 = (1.f - zz.x)*n0 + zz.x*h0o;
                float hn1 = (1.f - zz.y)*n1 + zz.y*h1o;
                h_sh[j*18 + bb0] = hn0;
                h_sh[j*18 + bb1] = hn1;
                hT[bb0*168 + j] = __float2half(hn0);
                hT[bb1*168 + j] = __float2half(hn1);
            }
        }
        __syncthreads();
    }

    for (int e = t; e < H_*16; e += 512){
        int j = e % H_, bb = e / H_;
        out[(b0 + bb)*(K_*H_) + k*H_ + j] = h_sh[j*18 + bb];
    }
}

// ---------------- launch (R14 schedule) ----------------
extern "C" void kernel_launch(void* const* d_in, const int* in_sizes, int n_in,
                              void* d_out, int out_size)
{
    const float* x       = (const float*)d_in[0];
    const float* y       = (const float*)d_in[1];
    const float* z_noise = (const float*)d_in[2];
    const float* lin_w   = (const float*)d_in[3];
    const float* lin_b   = (const float*)d_in[4];
    const float* a       = (const float*)d_in[5];
    const float* bias    = (const float*)d_in[6];
    const float* gl_wih  = (const float*)d_in[7];
    const float* gl_whh  = (const float*)d_in[8];
    const float* gl_bih  = (const float*)d_in[9];
    const float* gl_bhh  = (const float*)d_in[10];
    const float* mu_w    = (const float*)d_in[11];
    const float* mu_b    = (const float*)d_in[12];
    const float* std_w   = (const float*)d_in[13];
    const float* std_b   = (const float*)d_in[14];
    const float* net_wih = (const float*)d_in[15];
    const float* net_whh = (const float*)d_in[16];
    const float* net_bih = (const float*)d_in[17];
    const float* net_bhh = (const float*)d_in[18];
    float* out = (float*)d_out;

    static cudaStream_t s_side = nullptr;
    static cudaEvent_t ev1 = nullptr, ev2 = nullptr;
    if (!s_side){
        cudaStreamCreateWithFlags(&s_side, cudaStreamNonBlocking);
        cudaEventCreateWithFlags(&ev1, cudaEventDisableTiming);
        cudaEventCreateWithFlags(&ev2, cudaEventDisableTiming);
        cudaFuncSetAttribute(k_gxnet,   cudaFuncAttributeMaxDynamicSharedMemorySize,
                             GXM_SMEM_FLOATS*4);
        cudaFuncSetAttribute(k_gru_net, cudaFuncAttributeMaxDynamicSharedMemorySize,
                             GRN_SMEM_FLOATS*4);
        cudaFuncSetAttribute(k_gru_gl,  cudaFuncAttributeMaxDynamicSharedMemorySize,
                             GL_SMEM_FLOATS*4);
    }

    k_prep<<<256, 256, 0, s_side>>>(gl_wih, gl_whh, mu_w, std_w);

    k_wx<<<B_*K_, 128>>>(x, lin_w, lin_b);
    cudaEventRecord(ev1, 0);

    k_gxnet<<<K_*4, 512, GXM_SMEM_FLOATS*4>>>(net_wih, net_bih);

    cudaStreamWaitEvent(s_side, ev1, 0);
    k_attn<<<B_*K_, 256, 0, s_side>>>(y, a, bias);
    k_gxg<<<K_*B_, 512, 0, s_side>>>(gl_bih);
    k_gru_gl<<<B_*2, 256, GL_SMEM_FLOATS*4, s_side>>>(gl_bhh);
    k_z<<<B_, 160, 0, s_side>>>(mu_b, std_b, z_noise);
    cudaEventRecord(ev2, s_side);

    cudaStreamWaitEvent(0, ev2, 0);
    k_gru_net<<<K_*2, 512, GRN_SMEM_FLOATS*4>>>(net_whh, net_bhh, out);
}